// round 11
// baseline (speedup 1.0000x reference)
#include <cuda_runtime.h>
#include <cstdint>

#define BB   32
#define NNN  4096
#define EEE  8192
#define DDD  128
#define MTOT (BB * NNN)      // 131072 rows
#define EMSG (BB * EEE)      // 262144 messages

#define STRIDE_A 136
#define B_CHUNK  6144        // 6 mg * 16 o * 8 n * 8 words per 8-col block
#define NBLK     16
// smem: A1 [64][136] + A2 [64][136] + B chunk
#define A2_W   (64 * STRIDE_A)
#define B_W    (2 * 64 * STRIDE_A)
#define SMEM_WORDS (B_W + B_CHUNK)
#define SMEM_BYTES (SMEM_WORDS * 4)   // 94208 -> 2 CTAs/SM

// Device scratch (allocation-free rule: __device__ globals)
__device__ float    g_agg[(size_t)MTOT * DDD];     // 64 MB aggregated messages
__device__ uint32_t g_wf[NBLK * B_CHUNK];          // fragment-layout tf32 weights

__device__ __forceinline__ uint32_t f2tf32(float x) {
    uint32_t r;
    asm("cvt.rna.tf32.f32 %0, %1;" : "=r"(r) : "f"(x));
    return r;
}
__device__ __forceinline__ uint32_t smem_u32(const void* p) {
    uint32_t a;
    asm("{ .reg .u64 t; cvta.to.shared.u64 t, %1; cvt.u32.u64 %0, t; }" : "=r"(a) : "l"(p));
    return a;
}
#define CP_ASYNC16(dst, src) \
    asm volatile("cp.async.ca.shared.global [%0], [%1], 16;" :: "r"(dst), "l"(src) : "memory")
#define CP_COMMIT() asm volatile("cp.async.commit_group;" ::: "memory")
#define CP_WAIT0()  asm volatile("cp.async.wait_group 0;" ::: "memory")

// ---------------------------------------------------------------------------
// Kernel 1: zero the aggregation buffer
// ---------------------------------------------------------------------------
__global__ void zero_kernel() {
    size_t i = (size_t)blockIdx.x * blockDim.x + threadIdx.x;  // 4,194,304 float4s
    reinterpret_cast<float4*>(g_agg)[i] = make_float4(0.f, 0.f, 0.f, 0.f);
}

// ---------------------------------------------------------------------------
// Kernel 2: one-time weight prep into per-8-col-block fragment layout.
// c = ((mg*16 + o)*8 + n)*8 + 2*tt + p ; k = o*8 + tt + 4p ;
// mg = mat*3 + gate ; col = gate*128 + blk*8 + n.
// ---------------------------------------------------------------------------
__global__ void wprep_kernel(const float* __restrict__ W1,
                             const float* __restrict__ W2) {
    int i = blockIdx.x * blockDim.x + threadIdx.x;   // 98304
    int blk = i / B_CHUNK;
    int c   = i - blk * B_CHUNK;
    int mg  = c >> 10;
    int rem = c & 1023;
    int o   = rem >> 6;
    int rem2 = rem & 63;
    int n   = rem2 >> 3;
    int q   = rem2 & 7;
    int tt  = q >> 1, p = q & 1;
    int k   = o * 8 + tt + 4 * p;
    int mat = mg / 3, gate = mg - mat * 3;
    const float* W = mat ? W2 : W1;
    g_wf[i] = f2tf32(__ldg(&W[k * 384 + gate * 128 + blk * 8 + n]));
}

// ---------------------------------------------------------------------------
// Kernel 3: scatter-add messages (one warp per message, v4 global red)
// ---------------------------------------------------------------------------
__global__ void scatter_kernel(const float* __restrict__ msgs,
                               const int* __restrict__ conn) {
    unsigned u = blockIdx.x * blockDim.x + threadIdx.x;
    unsigned m = u >> 5, l = u & 31;
    int b = (int)(m >> 13);
    int tgt = 0;
    if (l == 0) tgt = __ldg(&conn[2 * m + 1]);
    tgt = __shfl_sync(0xffffffffu, tgt, 0);
    float4 v = reinterpret_cast<const float4*>(msgs)[(size_t)m * 32 + l];
    float* p = &g_agg[((size_t)((b << 12) + tgt)) * DDD + l * 4];
    asm volatile("red.global.add.v4.f32 [%0], {%1,%2,%3,%4};"
                 :: "l"(p), "f"(v.x), "f"(v.y), "f"(v.z), "f"(v.w) : "memory");
}

// ---------------------------------------------------------------------------
// Kernel 4: fused dual-GEMM (tf32 mma.sync) + GRU epilogue.
// CTA = 128 threads (4 warps), M=64 rows -> 94KB smem -> 2 CTAs/SM.
// 16 iterations x 8 gate-columns; B staged via cp.async.
// ---------------------------------------------------------------------------
#define MMA8(ac, A0, A1, A2, A3, B0, B1)                                       \
    asm volatile(                                                              \
        "mma.sync.aligned.m16n8k8.row.col.f32.tf32.tf32.f32 "                  \
        "{%0,%1,%2,%3},{%4,%5,%6,%7},{%8,%9},{%0,%1,%2,%3};"                   \
        : "+f"(ac[0]), "+f"(ac[1]), "+f"(ac[2]), "+f"(ac[3])                   \
        : "r"(A0), "r"(A1), "r"(A2), "r"(A3), "r"(B0), "r"(B1))

__global__ void __launch_bounds__(128, 2) fused_gru_kernel(
    const float* __restrict__ H,      // atom_state, [MTOT][128]
    const float* __restrict__ bias,   // [2][384]
    float* __restrict__ out)          // [MTOT][128]
{
    extern __shared__ uint32_t sm[];
    uint32_t* A1s = sm;                 // [64][STRIDE_A] tf32 (agg)
    uint32_t* A2s = sm + A2_W;          // [64][STRIDE_A] tf32 (h)
    uint32_t* Bs  = sm + B_W;           // B_CHUNK tf32 weight chunk

    const int tid  = threadIdx.x;
    const int warp = tid >> 5;          // 0..3 -> m16 strip
    const int lane = tid & 31;
    const int g    = lane >> 2;         // 0..7
    const int t    = lane & 3;          // 0..3
    const size_t rowBase = (size_t)blockIdx.x * 64;
    const uint32_t bs_base = smem_u32(Bs);

    // --- Stage A tiles (64 rows): vectorized convert + interleave.
    //     lo = {k0,k4,k1,k5}, hi = {k2,k6,k3,k7} at row*STRIDE_A + o*8.
    for (int gi = tid; gi < 1024; gi += 128) {
        int row = gi >> 4, o = gi & 15;
        const float* pa = &g_agg[(rowBase + row) * DDD + o * 8];
        const float* ph = &H[(rowBase + row) * DDD + o * 8];
        float4 a0 = *reinterpret_cast<const float4*>(pa);
        float4 a1 = *reinterpret_cast<const float4*>(pa + 4);
        float4 h0 = *reinterpret_cast<const float4*>(ph);
        float4 h1 = *reinterpret_cast<const float4*>(ph + 4);
        uint32_t* d1 = &A1s[row * STRIDE_A + o * 8];
        uint32_t* d2 = &A2s[row * STRIDE_A + o * 8];
        uint4 lo, hi;
        lo.x = f2tf32(a0.x); lo.y = f2tf32(a1.x); lo.z = f2tf32(a0.y); lo.w = f2tf32(a1.y);
        hi.x = f2tf32(a0.z); hi.y = f2tf32(a1.z); hi.z = f2tf32(a0.w); hi.w = f2tf32(a1.w);
        *reinterpret_cast<uint4*>(d1)     = lo;
        *reinterpret_cast<uint4*>(d1 + 4) = hi;
        lo.x = f2tf32(h0.x); lo.y = f2tf32(h1.x); lo.z = f2tf32(h0.y); lo.w = f2tf32(h1.y);
        hi.x = f2tf32(h0.z); hi.y = f2tf32(h1.z); hi.z = f2tf32(h0.w); hi.w = f2tf32(h1.w);
        *reinterpret_cast<uint4*>(d2)     = lo;
        *reinterpret_cast<uint4*>(d2 + 4) = hi;
    }

    const int r0 = warp * 16 + g;
    const float* b1p = bias;
    const float* b2p = bias + 384;

    for (int blk = 0; blk < NBLK; blk++) {
        __syncthreads();   // A ready (iter 0) / previous Bs consumers done

        // --- B chunk via cp.async: 1536 float4 / 128 threads = 12 each
        {
            const uint4* src = reinterpret_cast<const uint4*>(&g_wf[blk * B_CHUNK]);
#pragma unroll
            for (int v = 0; v < 12; v++)
                CP_ASYNC16(bs_base + (tid + v * 128) * 16, &src[tid + v * 128]);
            CP_COMMIT();
            CP_WAIT0();
        }
        __syncthreads();

        float acc[6][4];
#pragma unroll
        for (int i = 0; i < 6; i++)
#pragma unroll
            for (int j = 0; j < 4; j++) acc[i][j] = 0.f;

#pragma unroll 4
        for (int o = 0; o < 16; o++) {
            uint2 a1lo = *reinterpret_cast<const uint2*>(&A1s[r0 * STRIDE_A + o * 8 + 2 * t]);
            uint2 a1hi = *reinterpret_cast<const uint2*>(&A1s[(r0 + 8) * STRIDE_A + o * 8 + 2 * t]);
            uint2 a2lo = *reinterpret_cast<const uint2*>(&A2s[r0 * STRIDE_A + o * 8 + 2 * t]);
            uint2 a2hi = *reinterpret_cast<const uint2*>(&A2s[(r0 + 8) * STRIDE_A + o * 8 + 2 * t]);
            uint2 bf[6];
#pragma unroll
            for (int mg = 0; mg < 6; mg++)
                bf[mg] = *reinterpret_cast<const uint2*>(
                    &Bs[((mg * 16 + o) * 8 + g) * 8 + 2 * t]);
            MMA8(acc[0], a1lo.x, a1hi.x, a1lo.y, a1hi.y, bf[0].x, bf[0].y);
            MMA8(acc[1], a1lo.x, a1hi.x, a1lo.y, a1hi.y, bf[1].x, bf[1].y);
            MMA8(acc[2], a1lo.x, a1hi.x, a1lo.y, a1hi.y, bf[2].x, bf[2].y);
            MMA8(acc[3], a2lo.x, a2hi.x, a2lo.y, a2hi.y, bf[3].x, bf[3].y);
            MMA8(acc[4], a2lo.x, a2hi.x, a2lo.y, a2hi.y, bf[4].x, bf[4].y);
            MMA8(acc[5], a2lo.x, a2hi.x, a2lo.y, a2hi.y, bf[5].x, bf[5].y);
        }

        // --- GRU epilogue: thread owns rows {r0, r0+8} x cols {j0, j0+1}
        int j0 = blk * 8 + 2 * t;
#pragma unroll
        for (int half = 0; half < 2; half++) {
            size_t row = rowBase + r0 + half * 8;
            float2 h2 = *reinterpret_cast<const float2*>(&H[row * DDD + j0]);
            float o2[2];
#pragma unroll
            for (int cc = 0; cc < 2; cc++) {
                int j  = j0 + cc;
                int ai = half * 2 + cc;
                float xz = acc[0][ai] + b1p[j];
                float xr = acc[1][ai] + b1p[128 + j];
                float xh = acc[2][ai] + b1p[256 + j];
                float rz = acc[3][ai] + b2p[j];
                float rr = acc[4][ai] + b2p[128 + j];
                float rh = acc[5][ai] + b2p[256 + j];
                float z = 1.f / (1.f + __expf(-(xz + rz)));
                float r = 1.f / (1.f + __expf(-(xr + rr)));
                float e = __expf(2.f * (xh + r * rh));
                float hh = 1.f - 2.f / (e + 1.f);   // tanh
                float hv = (cc == 0) ? h2.x : h2.y;
                o2[cc] = z * hv + (1.f - z) * hh;
            }
            *reinterpret_cast<float2*>(&out[row * DDD + j0]) =
                make_float2(o2[0], o2[1]);
        }
    }
}

// ---------------------------------------------------------------------------
extern "C" void kernel_launch(void* const* d_in, const int* in_sizes, int n_in,
                              void* d_out, int out_size) {
    const float* atom = (const float*)d_in[0];
    const float* msgs = (const float*)d_in[1];
    const int*   conn = (const int*)d_in[2];
    const float* W1   = (const float*)d_in[3];
    const float* W2   = (const float*)d_in[4];
    const float* bias = (const float*)d_in[5];
    float* out = (float*)d_out;

    zero_kernel<<<16384, 256>>>();
    wprep_kernel<<<384, 256>>>(W1, W2);
    scatter_kernel<<<32768, 256>>>(msgs, conn);

    cudaFuncSetAttribute(fused_gru_kernel,
                         cudaFuncAttributeMaxDynamicSharedMemorySize,
                         SMEM_BYTES);
    fused_gru_kernel<<<MTOT / 64, 128, SMEM_BYTES>>>(atom, bias, out);
}

// round 15
// speedup vs baseline: 1.0389x; 1.0389x over previous
#include <cuda_runtime.h>
#include <cstdint>

#define BB   32
#define NNN  4096
#define EEE  8192
#define DDD  128
#define MTOT (BB * NNN)      // 131072 rows
#define EMSG (BB * EEE)      // 262144 messages

#define STRIDE_A 136
#define B_CHUNK  6144        // words per 8-col block (6 mg * 16 o * 8 n * 8)
#define B_CHUNK_B (B_CHUNK * 4)                // bytes per ring slot
#define NBLK     16
#define A2_W     (128 * STRIDE_A)
#define B_W      (2 * 128 * STRIDE_A)          // 34816 words
#define SMEM_WORDS (B_W + 3 * B_CHUNK)         // 53248 words
#define SMEM_BYTES (SMEM_WORDS * 4)            // 212992 B

// Device scratch (allocation-free rule: __device__ globals)
__device__ float    g_agg[(size_t)MTOT * DDD];     // 64 MB aggregated messages
__device__ uint32_t g_wf[NBLK * B_CHUNK];          // fragment-layout tf32 weights

__device__ __forceinline__ uint32_t f2tf32(float x) {
    uint32_t r;
    asm("cvt.rna.tf32.f32 %0, %1;" : "=r"(r) : "f"(x));
    return r;
}
__device__ __forceinline__ uint32_t smem_u32(const void* p) {
    uint32_t a;
    asm("{ .reg .u64 t; cvta.to.shared.u64 t, %1; cvt.u32.u64 %0, t; }" : "=r"(a) : "l"(p));
    return a;
}
#define CP_ASYNC16(dst, src) \
    asm volatile("cp.async.ca.shared.global [%0], [%1], 16;" :: "r"(dst), "l"(src) : "memory")
#define CP_COMMIT() asm volatile("cp.async.commit_group;" ::: "memory")
#define CP_WAIT1()  asm volatile("cp.async.wait_group 1;" ::: "memory")

// ---------------------------------------------------------------------------
// Kernel 1: zero the aggregation buffer
// ---------------------------------------------------------------------------
__global__ void zero_kernel() {
    size_t i = (size_t)blockIdx.x * blockDim.x + threadIdx.x;  // 4,194,304 float4s
    reinterpret_cast<float4*>(g_agg)[i] = make_float4(0.f, 0.f, 0.f, 0.f);
}

// ---------------------------------------------------------------------------
// Kernel 2: one-time weight prep into per-8-col-block fragment layout.
// c = ((mg*16 + o)*8 + n)*8 + 2*tt + p ; k = o*8 + tt + 4p ;
// mg = mat*3 + gate ; col = gate*128 + blk*8 + n.
// ---------------------------------------------------------------------------
__global__ void wprep_kernel(const float* __restrict__ W1,
                             const float* __restrict__ W2) {
    int i = blockIdx.x * blockDim.x + threadIdx.x;   // 98304
    int blk = i / B_CHUNK;
    int c   = i - blk * B_CHUNK;
    int mg  = c >> 10;
    int rem = c & 1023;
    int o   = rem >> 6;
    int rem2 = rem & 63;
    int n   = rem2 >> 3;
    int q   = rem2 & 7;
    int tt  = q >> 1, p = q & 1;
    int k   = o * 8 + tt + 4 * p;
    int mat = mg / 3, gate = mg - mat * 3;
    const float* W = mat ? W2 : W1;
    g_wf[i] = f2tf32(__ldg(&W[k * 384 + gate * 128 + blk * 8 + n]));
}

// ---------------------------------------------------------------------------
// Kernel 3: scatter-add messages (one warp per message, v4 global red)
// ---------------------------------------------------------------------------
__global__ void scatter_kernel(const float* __restrict__ msgs,
                               const int* __restrict__ conn) {
    unsigned u = blockIdx.x * blockDim.x + threadIdx.x;
    unsigned m = u >> 5, l = u & 31;
    int b = (int)(m >> 13);
    int tgt = 0;
    if (l == 0) tgt = __ldg(&conn[2 * m + 1]);
    tgt = __shfl_sync(0xffffffffu, tgt, 0);
    float4 v = reinterpret_cast<const float4*>(msgs)[(size_t)m * 32 + l];
    float* p = &g_agg[((size_t)((b << 12) + tgt)) * DDD + l * 4];
    asm volatile("red.global.add.v4.f32 [%0], {%1,%2,%3,%4};"
                 :: "l"(p), "f"(v.x), "f"(v.y), "f"(v.z), "f"(v.w) : "memory");
}

// ---------------------------------------------------------------------------
// Kernel 4: fused dual-GEMM (tf32 mma.sync) + GRU epilogue.
// CTA = 256 threads (8 warps), M=128 rows. 16 iterations x 8 gate-columns.
// B staged through a 3-deep cp.async ring: prefetch(blk+1) overlaps MMA(blk).
// One __syncthreads per iteration. Ring safety: slot (blk+1)%3 written at
// iter blk was last read at iter blk-2, and every warp passed sync(blk-1)
// only after fully finishing iter blk-2.
// ---------------------------------------------------------------------------
#define MMA8(ac, A0, A1, A2, A3, B0, B1)                                       \
    asm volatile(                                                              \
        "mma.sync.aligned.m16n8k8.row.col.f32.tf32.tf32.f32 "                  \
        "{%0,%1,%2,%3},{%4,%5,%6,%7},{%8,%9},{%0,%1,%2,%3};"                   \
        : "+f"(ac[0]), "+f"(ac[1]), "+f"(ac[2]), "+f"(ac[3])                   \
        : "r"(A0), "r"(A1), "r"(A2), "r"(A3), "r"(B0), "r"(B1))

__global__ void __launch_bounds__(256, 1) fused_gru_kernel(
    const float* __restrict__ H,      // atom_state, [MTOT][128]
    const float* __restrict__ bias,   // [2][384]
    float* __restrict__ out)          // [MTOT][128]
{
    extern __shared__ uint32_t sm[];
    uint32_t* A1s = sm;                 // [128][STRIDE_A] tf32 (agg)
    uint32_t* A2s = sm + A2_W;          // [128][STRIDE_A] tf32 (h)
    uint32_t* Bs  = sm + B_W;           // 3 x B_CHUNK ring (words)

    const int tid  = threadIdx.x;
    const int warp = tid >> 5;          // 0..7 -> m16 strip
    const int lane = tid & 31;
    const int g    = lane >> 2;         // 0..7
    const int t    = lane & 3;          // 0..3
    const size_t rowBase = (size_t)blockIdx.x * 128;
    const uint32_t bs_base = smem_u32(Bs);

    // --- Prologue: prefetch B block 0 into ring slot 0 (overlaps A staging)
    {
        const uint4* src = reinterpret_cast<const uint4*>(&g_wf[0]);
#pragma unroll
        for (int v = 0; v < 6; v++)
            CP_ASYNC16(bs_base + (uint32_t)(tid + v * 256) * 16, &src[tid + v * 256]);
        CP_COMMIT();
    }

    // --- Stage A tiles (128 rows): vectorized convert + interleave.
    //     lo = {k0,k4,k1,k5}, hi = {k2,k6,k3,k7} at row*STRIDE_A + o*8.
    for (int gi = tid; gi < 2048; gi += 256) {
        int row = gi >> 4, o = gi & 15;
        const float* pa = &g_agg[(rowBase + row) * DDD + o * 8];
        const float* ph = &H[(rowBase + row) * DDD + o * 8];
        float4 a0 = *reinterpret_cast<const float4*>(pa);
        float4 a1 = *reinterpret_cast<const float4*>(pa + 4);
        float4 h0 = *reinterpret_cast<const float4*>(ph);
        float4 h1 = *reinterpret_cast<const float4*>(ph + 4);
        uint32_t* d1 = &A1s[row * STRIDE_A + o * 8];
        uint32_t* d2 = &A2s[row * STRIDE_A + o * 8];
        uint4 lo, hi;
        lo.x = f2tf32(a0.x); lo.y = f2tf32(a1.x); lo.z = f2tf32(a0.y); lo.w = f2tf32(a1.y);
        hi.x = f2tf32(a0.z); hi.y = f2tf32(a1.z); hi.z = f2tf32(a0.w); hi.w = f2tf32(a1.w);
        *reinterpret_cast<uint4*>(d1)     = lo;
        *reinterpret_cast<uint4*>(d1 + 4) = hi;
        lo.x = f2tf32(h0.x); lo.y = f2tf32(h1.x); lo.z = f2tf32(h0.y); lo.w = f2tf32(h1.y);
        hi.x = f2tf32(h0.z); hi.y = f2tf32(h1.z); hi.z = f2tf32(h0.w); hi.w = f2tf32(h1.w);
        *reinterpret_cast<uint4*>(d2)     = lo;
        *reinterpret_cast<uint4*>(d2 + 4) = hi;
    }

    const int r0 = warp * 16 + g;
    const float* b1p = bias;
    const float* b2p = bias + 384;

    for (int blk = 0; blk < NBLK; blk++) {
        const int rbuf = blk % 3;
        const int wbuf = (blk + 1) % 3;
        const int nb   = (blk + 1) & 15;   // wraps to 0 on last iter (harmless)

        // --- Prefetch next B block into ring slot wbuf (BYTE offsets!)
        {
            const uint4* src = reinterpret_cast<const uint4*>(&g_wf[nb * B_CHUNK]);
            const uint32_t dst0 = bs_base + (uint32_t)wbuf * B_CHUNK_B;
#pragma unroll
            for (int v = 0; v < 6; v++)
                CP_ASYNC16(dst0 + (uint32_t)(tid + v * 256) * 16, &src[tid + v * 256]);
            CP_COMMIT();
        }
        CP_WAIT1();          // drain the group committed last iteration
        __syncthreads();     // all warps past iter blk-2; slot rbuf ready

        const uint32_t* Bp = Bs + rbuf * B_CHUNK;

        float acc[6][4];
#pragma unroll
        for (int i = 0; i < 6; i++)
#pragma unroll
            for (int j = 0; j < 4; j++) acc[i][j] = 0.f;

#pragma unroll 4
        for (int o = 0; o < 16; o++) {
            uint2 a1lo = *reinterpret_cast<const uint2*>(&A1s[r0 * STRIDE_A + o * 8 + 2 * t]);
            uint2 a1hi = *reinterpret_cast<const uint2*>(&A1s[(r0 + 8) * STRIDE_A + o * 8 + 2 * t]);
            uint2 a2lo = *reinterpret_cast<const uint2*>(&A2s[r0 * STRIDE_A + o * 8 + 2 * t]);
            uint2 a2hi = *reinterpret_cast<const uint2*>(&A2s[(r0 + 8) * STRIDE_A + o * 8 + 2 * t]);
            uint2 bf[6];
#pragma unroll
            for (int mg = 0; mg < 6; mg++)
                bf[mg] = *reinterpret_cast<const uint2*>(
                    &Bp[((mg * 16 + o) * 8 + g) * 8 + 2 * t]);
            MMA8(acc[0], a1lo.x, a1hi.x, a1lo.y, a1hi.y, bf[0].x, bf[0].y);
            MMA8(acc[1], a1lo.x, a1hi.x, a1lo.y, a1hi.y, bf[1].x, bf[1].y);
            MMA8(acc[2], a1lo.x, a1hi.x, a1lo.y, a1hi.y, bf[2].x, bf[2].y);
            MMA8(acc[3], a2lo.x, a2hi.x, a2lo.y, a2hi.y, bf[3].x, bf[3].y);
            MMA8(acc[4], a2lo.x, a2hi.x, a2lo.y, a2hi.y, bf[4].x, bf[4].y);
            MMA8(acc[5], a2lo.x, a2hi.x, a2lo.y, a2hi.y, bf[5].x, bf[5].y);
        }

        // --- GRU epilogue: thread owns rows {r0, r0+8} x cols {j0, j0+1}
        int j0 = blk * 8 + 2 * t;
#pragma unroll
        for (int half = 0; half < 2; half++) {
            size_t row = rowBase + r0 + half * 8;
            float2 h2 = *reinterpret_cast<const float2*>(&H[row * DDD + j0]);
            float o2[2];
#pragma unroll
            for (int cc = 0; cc < 2; cc++) {
                int j  = j0 + cc;
                int ai = half * 2 + cc;
                float xz = acc[0][ai] + b1p[j];
                float xr = acc[1][ai] + b1p[128 + j];
                float xh = acc[2][ai] + b1p[256 + j];
                float rz = acc[3][ai] + b2p[j];
                float rr = acc[4][ai] + b2p[128 + j];
                float rh = acc[5][ai] + b2p[256 + j];
                float z = 1.f / (1.f + __expf(-(xz + rz)));
                float r = 1.f / (1.f + __expf(-(xr + rr)));
                float e = __expf(2.f * (xh + r * rh));
                float hh = 1.f - 2.f / (e + 1.f);   // tanh
                float hv = (cc == 0) ? h2.x : h2.y;
                o2[cc] = z * hv + (1.f - z) * hh;
            }
            *reinterpret_cast<float2*>(&out[row * DDD + j0]) =
                make_float2(o2[0], o2[1]);
        }
    }
}

// ---------------------------------------------------------------------------
extern "C" void kernel_launch(void* const* d_in, const int* in_sizes, int n_in,
                              void* d_out, int out_size) {
    const float* atom = (const float*)d_in[0];
    const float* msgs = (const float*)d_in[1];
    const int*   conn = (const int*)d_in[2];
    const float* W1   = (const float*)d_in[3];
    const float* W2   = (const float*)d_in[4];
    const float* bias = (const float*)d_in[5];
    float* out = (float*)d_out;

    zero_kernel<<<16384, 256>>>();
    wprep_kernel<<<384, 256>>>(W1, W2);
    scatter_kernel<<<32768, 256>>>(msgs, conn);

    cudaFuncSetAttribute(fused_gru_kernel,
                         cudaFuncAttributeMaxDynamicSharedMemorySize,
                         SMEM_BYTES);
    fused_gru_kernel<<<MTOT / 128, 256, SMEM_BYTES>>>(atom, bias, out);
}

// round 16
// speedup vs baseline: 1.1425x; 1.0997x over previous
#include <cuda_runtime.h>
#include <cstdint>

#define MTOT 131072
#define DDD  128

#define STRIDE_A 144                  // words; mod 32 == 16 for LDS.128 phases
#define A_W     (128 * STRIDE_A)      // 18432 words per A tile
#define B_OFFW  (2 * A_W)             // 36864
#define B_CHUNK 12288                 // words per 16-col block (6mg*16o*16n*8)
#define NBLK    8
#define SMEM_WORDS (B_OFFW + B_CHUNK) // 49152
#define SMEM_BYTES (SMEM_WORDS * 4)   // 196608 B

// Device scratch (allocation-free rule: __device__ globals)
__device__ float    g_agg[(size_t)MTOT * DDD];   // 64 MB aggregated messages
__device__ uint32_t g_wf[NBLK * B_CHUNK];        // fragment-layout tf32 weights
__device__ float    g_bias[4 * DDD];             // [gz | gr | gxh | grh]

__device__ __forceinline__ uint32_t f2tf32(float x) {
    uint32_t r;
    asm("cvt.rna.tf32.f32 %0, %1;" : "=r"(r) : "f"(x));
    return r;
}
__device__ __forceinline__ uint32_t smem_u32(const void* p) {
    uint32_t a;
    asm("{ .reg .u64 t; cvta.to.shared.u64 t, %1; cvt.u32.u64 %0, t; }" : "=r"(a) : "l"(p));
    return a;
}
#define CP_ASYNC16(dst, src) \
    asm volatile("cp.async.ca.shared.global [%0], [%1], 16;" :: "r"(dst), "l"(src) : "memory")
#define CP_COMMIT() asm volatile("cp.async.commit_group;" ::: "memory")
#define CP_WAIT0()  asm volatile("cp.async.wait_group 0;" ::: "memory")

// ---------------------------------------------------------------------------
// Kernel 1: zero the aggregation buffer
// ---------------------------------------------------------------------------
__global__ void zero_kernel() {
    size_t i = (size_t)blockIdx.x * blockDim.x + threadIdx.x;  // 4,194,304 float4s
    reinterpret_cast<float4*>(g_agg)[i] = make_float4(0.f, 0.f, 0.f, 0.f);
}

// ---------------------------------------------------------------------------
// Kernel 2: one-time weight prep into per-16-col-block fragment layout
// (round-8 mapping) + pre-combined GRU biases.
// c = ((mg*16 + o)*16 + n)*8 + 2*tt + p ; k = o*8 + tt + 4p ;
// mg = mat*3 + gate ; col = gate*128 + blk*16 + n.
// ---------------------------------------------------------------------------
__global__ void wprep_kernel(const float* __restrict__ W1,
                             const float* __restrict__ W2,
                             const float* __restrict__ bias) {
    int i = blockIdx.x * blockDim.x + threadIdx.x;   // 98304
    if (i < 4 * DDD) {
        int a = i >> 7, j = i & 127;
        float v;
        if (a == 0)      v = bias[j]       + bias[384 + j];   // z-sum bias
        else if (a == 1) v = bias[128 + j] + bias[512 + j];   // r-sum bias
        else if (a == 2) v = bias[256 + j];                   // x_h bias
        else             v = bias[640 + j];                   // r_h bias
        g_bias[i] = v;
    }
    int blk = i / B_CHUNK;
    int c   = i - blk * B_CHUNK;
    int mg  = c >> 11;
    int rem = c & 2047;
    int o   = rem >> 7;
    int rem2 = rem & 127;
    int n   = rem2 >> 3;
    int q   = rem2 & 7;
    int tt  = q >> 1, p = q & 1;
    int k   = o * 8 + tt + 4 * p;
    int mat = mg / 3, gate = mg - mat * 3;
    const float* W = mat ? W2 : W1;
    g_wf[i] = f2tf32(__ldg(&W[k * 384 + gate * 128 + blk * 16 + n]));
}

// ---------------------------------------------------------------------------
// Kernel 3: scatter-add messages (one warp per message, v4 global red)
// ---------------------------------------------------------------------------
__global__ void scatter_kernel(const float* __restrict__ msgs,
                               const int* __restrict__ conn) {
    unsigned u = blockIdx.x * blockDim.x + threadIdx.x;
    unsigned m = u >> 5, l = u & 31;
    int b = (int)(m >> 13);
    int tgt = 0;
    if (l == 0) tgt = __ldg(&conn[2 * m + 1]);
    tgt = __shfl_sync(0xffffffffu, tgt, 0);
    float4 v = reinterpret_cast<const float4*>(msgs)[(size_t)m * 32 + l];
    float* p = &g_agg[((size_t)((b << 12) + tgt)) * DDD + l * 4];
    asm volatile("red.global.add.v4.f32 [%0], {%1,%2,%3,%4};"
                 :: "l"(p), "f"(v.x), "f"(v.y), "f"(v.z), "f"(v.w) : "memory");
}

// ---------------------------------------------------------------------------
// Kernel 4: fused dual-GEMM (tf32 mma.sync) + GRU epilogue.
// CTA = 256 threads (8 warps), M=128. 8 iterations x 16 gate-columns,
// 12 accumulators (round-8 champion shape). New this round:
//  - A pair-interleaved layout -> LDS.128 serves two k-octets at once.
//    Word at row*144 + P*16 + half*2 + (q&3)*4 + (q>>2), q = k & 7.
//    uint4 @ [r*144 + P*16 + 4t] = {A(r,16P+t), A(r,16P+4+t),
//                                   A(r,16P+8+t), A(r,16P+12+t)}
//    = o-even frag (.x,.y) and o-odd frag (.z,.w).
//  - B smem fill via cp.async (no register staging).
//  - Epilogue H/bias operands prefetched before the MMA loop.
// ---------------------------------------------------------------------------
#define MMA8(ac, A0, A1, A2, A3, B0, B1)                                       \
    asm volatile(                                                              \
        "mma.sync.aligned.m16n8k8.row.col.f32.tf32.tf32.f32 "                  \
        "{%0,%1,%2,%3},{%4,%5,%6,%7},{%8,%9},{%0,%1,%2,%3};"                   \
        : "+f"(ac[0]), "+f"(ac[1]), "+f"(ac[2]), "+f"(ac[3])                   \
        : "r"(A0), "r"(A1), "r"(A2), "r"(A3), "r"(B0), "r"(B1))

__global__ void __launch_bounds__(256, 1) fused_gru_kernel(
    const float* __restrict__ H,      // atom_state, [MTOT][128]
    float* __restrict__ out)          // [MTOT][128]
{
    extern __shared__ uint32_t sm[];
    uint32_t* A1s = sm;               // [128][144] tf32 (agg), pair layout
    uint32_t* A2s = sm + A_W;         // [128][144] tf32 (h), pair layout
    uint32_t* Bs  = sm + B_OFFW;      // B_CHUNK weight chunk

    const int tid  = threadIdx.x;
    const int warp = tid >> 5;        // 0..7 -> m16 strip
    const int lane = tid & 31;
    const int g    = lane >> 2;       // 0..7
    const int t    = lane & 3;        // 0..3
    const size_t rowBase = (size_t)blockIdx.x * 128;
    const uint32_t bs_base = smem_u32(Bs);

    // --- Stage A tiles in the pair-interleaved layout.
    for (int gi = tid; gi < 2048; gi += 256) {
        int row = gi >> 4, o = gi & 15;
        int P = o >> 1, half = o & 1;
        const float* pa = &g_agg[(rowBase + row) * DDD + o * 8];
        const float* ph = &H[(rowBase + row) * DDD + o * 8];
        float4 a0 = *reinterpret_cast<const float4*>(pa);
        float4 a1 = *reinterpret_cast<const float4*>(pa + 4);
        float4 h0 = *reinterpret_cast<const float4*>(ph);
        float4 h1 = *reinterpret_cast<const float4*>(ph + 4);
        uint32_t* d1 = &A1s[row * STRIDE_A + P * 16 + half * 2];
        uint32_t* d2 = &A2s[row * STRIDE_A + P * 16 + half * 2];
        // pairs (q, q+4) -> uint2 at word offsets {0,4,8,12}
        *reinterpret_cast<uint2*>(d1 + 0)  = make_uint2(f2tf32(a0.x), f2tf32(a1.x));
        *reinterpret_cast<uint2*>(d1 + 4)  = make_uint2(f2tf32(a0.y), f2tf32(a1.y));
        *reinterpret_cast<uint2*>(d1 + 8)  = make_uint2(f2tf32(a0.z), f2tf32(a1.z));
        *reinterpret_cast<uint2*>(d1 + 12) = make_uint2(f2tf32(a0.w), f2tf32(a1.w));
        *reinterpret_cast<uint2*>(d2 + 0)  = make_uint2(f2tf32(h0.x), f2tf32(h1.x));
        *reinterpret_cast<uint2*>(d2 + 4)  = make_uint2(f2tf32(h0.y), f2tf32(h1.y));
        *reinterpret_cast<uint2*>(d2 + 8)  = make_uint2(f2tf32(h0.z), f2tf32(h1.z));
        *reinterpret_cast<uint2*>(d2 + 12) = make_uint2(f2tf32(h0.w), f2tf32(h1.w));
    }

    const int r0 = warp * 16 + g;

    for (int blk = 0; blk < NBLK; blk++) {
        __syncthreads();   // previous Bs consumers done / A ready (iter 0)

        // --- B chunk via cp.async: 3072 float4 / 256 threads = 12 each
        {
            const uint4* src = reinterpret_cast<const uint4*>(&g_wf[blk * B_CHUNK]);
#pragma unroll
            for (int v = 0; v < 12; v++)
                CP_ASYNC16(bs_base + (uint32_t)(tid + v * 256) * 16, &src[tid + v * 256]);
            CP_COMMIT();
        }

        // --- Prefetch epilogue operands (hidden under the MMA loop)
        const int j00 = blk * 16 + 2 * t;        // n8 = 0
        const int j01 = j00 + 8;                 // n8 = 1
        float2 hpre[2][2];                       // [half][n8]
#pragma unroll
        for (int half = 0; half < 2; half++) {
            size_t row = rowBase + r0 + half * 8;
            hpre[half][0] = *reinterpret_cast<const float2*>(&H[row * DDD + j00]);
            hpre[half][1] = *reinterpret_cast<const float2*>(&H[row * DDD + j01]);
        }
        float bz[2][2], br[2][2], bxh[2][2], brh[2][2];   // [n8][cc]
#pragma unroll
        for (int n8 = 0; n8 < 2; n8++)
#pragma unroll
            for (int cc = 0; cc < 2; cc++) {
                int j = (n8 ? j01 : j00) + cc;
                bz[n8][cc]  = __ldg(&g_bias[j]);
                br[n8][cc]  = __ldg(&g_bias[128 + j]);
                bxh[n8][cc] = __ldg(&g_bias[256 + j]);
                brh[n8][cc] = __ldg(&g_bias[384 + j]);
            }

        CP_WAIT0();
        __syncthreads();   // Bs ready

        float acc[12][4];            // [n8*6 + mg][frag]
#pragma unroll
        for (int i = 0; i < 12; i++)
#pragma unroll
            for (int j = 0; j < 4; j++) acc[i][j] = 0.f;

#pragma unroll
        for (int P = 0; P < 8; P++) {
            uint4 A1lo = *reinterpret_cast<const uint4*>(&A1s[r0 * STRIDE_A + P * 16 + 4 * t]);
            uint4 A1hi = *reinterpret_cast<const uint4*>(&A1s[(r0 + 8) * STRIDE_A + P * 16 + 4 * t]);
            uint4 A2lo = *reinterpret_cast<const uint4*>(&A2s[r0 * STRIDE_A + P * 16 + 4 * t]);
            uint4 A2hi = *reinterpret_cast<const uint4*>(&A2s[(r0 + 8) * STRIDE_A + P * 16 + 4 * t]);
#pragma unroll
            for (int oo = 0; oo < 2; oo++) {
                const int o = 2 * P + oo;
                const uint32_t a1_0 = oo ? A1lo.z : A1lo.x;   // (r0,   k+t)
                const uint32_t a1_1 = oo ? A1hi.z : A1hi.x;   // (r0+8, k+t)
                const uint32_t a1_2 = oo ? A1lo.w : A1lo.y;   // (r0,   k+t+4)
                const uint32_t a1_3 = oo ? A1hi.w : A1hi.y;   // (r0+8, k+t+4)
                const uint32_t a2_0 = oo ? A2lo.z : A2lo.x;
                const uint32_t a2_1 = oo ? A2hi.z : A2hi.x;
                const uint32_t a2_2 = oo ? A2lo.w : A2lo.y;
                const uint32_t a2_3 = oo ? A2hi.w : A2hi.y;
#pragma unroll
                for (int n8 = 0; n8 < 2; n8++) {
                    uint2 bf[6];
#pragma unroll
                    for (int mg = 0; mg < 6; mg++)
                        bf[mg] = *reinterpret_cast<const uint2*>(
                            &Bs[((mg * 16 + o) * 16 + n8 * 8 + g) * 8 + 2 * t]);
                    MMA8(acc[n8 * 6 + 0], a1_0, a1_1, a1_2, a1_3, bf[0].x, bf[0].y);
                    MMA8(acc[n8 * 6 + 1], a1_0, a1_1, a1_2, a1_3, bf[1].x, bf[1].y);
                    MMA8(acc[n8 * 6 + 2], a1_0, a1_1, a1_2, a1_3, bf[2].x, bf[2].y);
                    MMA8(acc[n8 * 6 + 3], a2_0, a2_1, a2_2, a2_3, bf[3].x, bf[3].y);
                    MMA8(acc[n8 * 6 + 4], a2_0, a2_1, a2_2, a2_3, bf[4].x, bf[4].y);
                    MMA8(acc[n8 * 6 + 5], a2_0, a2_1, a2_2, a2_3, bf[5].x, bf[5].y);
                }
            }
        }

        // --- GRU epilogue from prefetched operands
#pragma unroll
        for (int n8 = 0; n8 < 2; n8++) {
            int j0 = n8 ? j01 : j00;
#pragma unroll
            for (int half = 0; half < 2; half++) {
                size_t row = rowBase + r0 + half * 8;
                float o2[2];
#pragma unroll
                for (int cc = 0; cc < 2; cc++) {
                    int ai = half * 2 + cc;
                    float zin = acc[n8 * 6 + 0][ai] + acc[n8 * 6 + 3][ai] + bz[n8][cc];
                    float rin = acc[n8 * 6 + 1][ai] + acc[n8 * 6 + 4][ai] + br[n8][cc];
                    float xh  = acc[n8 * 6 + 2][ai] + bxh[n8][cc];
                    float rh  = acc[n8 * 6 + 5][ai] + brh[n8][cc];
                    float z = 1.f / (1.f + __expf(-zin));
                    float r = 1.f / (1.f + __expf(-rin));
                    float e = __expf(2.f * (xh + r * rh));
                    float hh = 1.f - 2.f / (e + 1.f);   // tanh
                    float hv = (cc == 0) ? hpre[half][n8].x : hpre[half][n8].y;
                    o2[cc] = z * hv + (1.f - z) * hh;
                }
                *reinterpret_cast<float2*>(&out[row * DDD + j0]) =
                    make_float2(o2[0], o2[1]);
            }
        }
    }
}

// ---------------------------------------------------------------------------
extern "C" void kernel_launch(void* const* d_in, const int* in_sizes, int n_in,
                              void* d_out, int out_size) {
    const float* atom = (const float*)d_in[0];
    const float* msgs = (const float*)d_in[1];
    const int*   conn = (const int*)d_in[2];
    const float* W1   = (const float*)d_in[3];
    const float* W2   = (const float*)d_in[4];
    const float* bias = (const float*)d_in[5];
    float* out = (float*)d_out;

    zero_kernel<<<16384, 256>>>();
    wprep_kernel<<<384, 256>>>(W1, W2, bias);
    scatter_kernel<<<32768, 256>>>(msgs, conn);

    cudaFuncSetAttribute(fused_gru_kernel,
                         cudaFuncAttributeMaxDynamicSharedMemorySize,
                         SMEM_BYTES);
    fused_gru_kernel<<<MTOT / 128, 256, SMEM_BYTES>>>(atom, out);
}

// round 17
// speedup vs baseline: 1.2187x; 1.0667x over previous
#include <cuda_runtime.h>
#include <cstdint>

#define MTOT 131072
#define DDD  128

#define STRIDE_A 144                  // words; mod 32 == 16 for LDS.128 phases
#define A_W     (128 * STRIDE_A)      // 18432 words per A tile
#define B_OFFW  (2 * A_W)             // 36864
#define B_CHUNK 12288                 // words per 16-col block (6mg*16o*16n*8)
#define NBLK    8
#define SMEM_WORDS (B_OFFW + B_CHUNK) // 49152
#define SMEM_BYTES (SMEM_WORDS * 4)   // 196608 B

// Device scratch (allocation-free rule: __device__ globals)
__device__ float    g_agg[(size_t)MTOT * DDD];   // 64 MB aggregated messages
__device__ uint32_t g_wf[NBLK * B_CHUNK];        // fragment-layout tf32 weights
__device__ float    g_bias[4 * DDD];             // [gz | gr | gxh | grh]

__device__ __forceinline__ uint32_t f2tf32(float x) {
    uint32_t r;
    asm("cvt.rna.tf32.f32 %0, %1;" : "=r"(r) : "f"(x));
    return r;
}
__device__ __forceinline__ uint32_t smem_u32(const void* p) {
    uint32_t a;
    asm("{ .reg .u64 t; cvta.to.shared.u64 t, %1; cvt.u32.u64 %0, t; }" : "=r"(a) : "l"(p));
    return a;
}
#define CP_ASYNC16(dst, src) \
    asm volatile("cp.async.ca.shared.global [%0], [%1], 16;" :: "r"(dst), "l"(src) : "memory")
#define CP_COMMIT() asm volatile("cp.async.commit_group;" ::: "memory")
#define CP_WAIT0()  asm volatile("cp.async.wait_group 0;" ::: "memory")

// ---------------------------------------------------------------------------
// Kernel 1: zero the aggregation buffer
// ---------------------------------------------------------------------------
__global__ void zero_kernel() {
    size_t i = (size_t)blockIdx.x * blockDim.x + threadIdx.x;  // 4,194,304 float4s
    reinterpret_cast<float4*>(g_agg)[i] = make_float4(0.f, 0.f, 0.f, 0.f);
}

// ---------------------------------------------------------------------------
// Kernel 2: one-time weight prep into per-16-col-block fragment layout
// + pre-combined GRU biases.
// c = ((mg*16 + o)*16 + n)*8 + 2*tt + p ; k = o*8 + tt + 4p ;
// mg = mat*3 + gate ; col = gate*128 + blk*16 + n.
// ---------------------------------------------------------------------------
__global__ void wprep_kernel(const float* __restrict__ W1,
                             const float* __restrict__ W2,
                             const float* __restrict__ bias) {
    int i = blockIdx.x * blockDim.x + threadIdx.x;   // 98304
    if (i < 4 * DDD) {
        int a = i >> 7, j = i & 127;
        float v;
        if (a == 0)      v = bias[j]       + bias[384 + j];   // z-sum bias
        else if (a == 1) v = bias[128 + j] + bias[512 + j];   // r-sum bias
        else if (a == 2) v = bias[256 + j];                   // x_h bias
        else             v = bias[640 + j];                   // r_h bias
        g_bias[i] = v;
    }
    int blk = i / B_CHUNK;
    int c   = i - blk * B_CHUNK;
    int mg  = c >> 11;
    int rem = c & 2047;
    int o   = rem >> 7;
    int rem2 = rem & 127;
    int n   = rem2 >> 3;
    int q   = rem2 & 7;
    int tt  = q >> 1, p = q & 1;
    int k   = o * 8 + tt + 4 * p;
    int mat = mg / 3, gate = mg - mat * 3;
    const float* W = mat ? W2 : W1;
    g_wf[i] = f2tf32(__ldg(&W[k * 384 + gate * 128 + blk * 16 + n]));
}

// ---------------------------------------------------------------------------
// Kernel 3: scatter-add messages (one warp per message, v4 global red)
// ---------------------------------------------------------------------------
__global__ void scatter_kernel(const float* __restrict__ msgs,
                               const int* __restrict__ conn) {
    unsigned u = blockIdx.x * blockDim.x + threadIdx.x;
    unsigned m = u >> 5, l = u & 31;
    int b = (int)(m >> 13);
    int tgt = 0;
    if (l == 0) tgt = __ldg(&conn[2 * m + 1]);
    tgt = __shfl_sync(0xffffffffu, tgt, 0);
    float4 v = reinterpret_cast<const float4*>(msgs)[(size_t)m * 32 + l];
    float* p = &g_agg[((size_t)((b << 12) + tgt)) * DDD + l * 4];
    asm volatile("red.global.add.v4.f32 [%0], {%1,%2,%3,%4};"
                 :: "l"(p), "f"(v.x), "f"(v.y), "f"(v.z), "f"(v.w) : "memory");
}

// ---------------------------------------------------------------------------
// Kernel 4: fused dual-GEMM (tf32 mma.sync) + GRU epilogue.
// CTA = 512 threads (16 warps) = 8 m-strips x 2 n8-halves, M=128 tile.
// Same smem/layouts as round 16; per-warp work halves (6 accumulators),
// warps/SMSP doubles 2 -> 4 for latency hiding.
// ---------------------------------------------------------------------------
#define MMA8(ac, A0, A1, A2, A3, B0, B1)                                       \
    asm volatile(                                                              \
        "mma.sync.aligned.m16n8k8.row.col.f32.tf32.tf32.f32 "                  \
        "{%0,%1,%2,%3},{%4,%5,%6,%7},{%8,%9},{%0,%1,%2,%3};"                   \
        : "+f"(ac[0]), "+f"(ac[1]), "+f"(ac[2]), "+f"(ac[3])                   \
        : "r"(A0), "r"(A1), "r"(A2), "r"(A3), "r"(B0), "r"(B1))

__global__ void __launch_bounds__(512, 1) fused_gru_kernel(
    const float* __restrict__ H,      // atom_state, [MTOT][128]
    float* __restrict__ out)          // [MTOT][128]
{
    extern __shared__ uint32_t sm[];
    uint32_t* A1s = sm;               // [128][144] tf32 (agg), pair layout
    uint32_t* A2s = sm + A_W;         // [128][144] tf32 (h), pair layout
    uint32_t* Bs  = sm + B_OFFW;      // B_CHUNK weight chunk

    const int tid  = threadIdx.x;
    const int warp = tid >> 5;        // 0..15
    const int ms   = warp & 7;        // m16 strip
    const int n8   = warp >> 3;       // n8 half (0/1)
    const int lane = tid & 31;
    const int g    = lane >> 2;       // 0..7
    const int t    = lane & 3;        // 0..3
    const size_t rowBase = (size_t)blockIdx.x * 128;
    const uint32_t bs_base = smem_u32(Bs);

    // --- Stage A tiles in the pair-interleaved layout (2048 items / 512 thr).
    for (int gi = tid; gi < 2048; gi += 512) {
        int row = gi >> 4, o = gi & 15;
        int P = o >> 1, half = o & 1;
        const float* pa = &g_agg[(rowBase + row) * DDD + o * 8];
        const float* ph = &H[(rowBase + row) * DDD + o * 8];
        float4 a0 = *reinterpret_cast<const float4*>(pa);
        float4 a1 = *reinterpret_cast<const float4*>(pa + 4);
        float4 h0 = *reinterpret_cast<const float4*>(ph);
        float4 h1 = *reinterpret_cast<const float4*>(ph + 4);
        uint32_t* d1 = &A1s[row * STRIDE_A + P * 16 + half * 2];
        uint32_t* d2 = &A2s[row * STRIDE_A + P * 16 + half * 2];
        *reinterpret_cast<uint2*>(d1 + 0)  = make_uint2(f2tf32(a0.x), f2tf32(a1.x));
        *reinterpret_cast<uint2*>(d1 + 4)  = make_uint2(f2tf32(a0.y), f2tf32(a1.y));
        *reinterpret_cast<uint2*>(d1 + 8)  = make_uint2(f2tf32(a0.z), f2tf32(a1.z));
        *reinterpret_cast<uint2*>(d1 + 12) = make_uint2(f2tf32(a0.w), f2tf32(a1.w));
        *reinterpret_cast<uint2*>(d2 + 0)  = make_uint2(f2tf32(h0.x), f2tf32(h1.x));
        *reinterpret_cast<uint2*>(d2 + 4)  = make_uint2(f2tf32(h0.y), f2tf32(h1.y));
        *reinterpret_cast<uint2*>(d2 + 8)  = make_uint2(f2tf32(h0.z), f2tf32(h1.z));
        *reinterpret_cast<uint2*>(d2 + 12) = make_uint2(f2tf32(h0.w), f2tf32(h1.w));
    }

    const int r0 = ms * 16 + g;

    for (int blk = 0; blk < NBLK; blk++) {
        __syncthreads();   // previous Bs consumers done / A ready (iter 0)

        // --- B chunk via cp.async: 3072 float4 / 512 threads = 6 each
        {
            const uint4* src = reinterpret_cast<const uint4*>(&g_wf[blk * B_CHUNK]);
#pragma unroll
            for (int v = 0; v < 6; v++)
                CP_ASYNC16(bs_base + (uint32_t)(tid + v * 512) * 16, &src[tid + v * 512]);
            CP_COMMIT();
        }

        // --- Prefetch epilogue operands (hidden under the MMA loop)
        const int j0 = blk * 16 + n8 * 8 + 2 * t;
        float2 hpre[2];                           // [half]
#pragma unroll
        for (int half = 0; half < 2; half++)
            hpre[half] = *reinterpret_cast<const float2*>(
                &H[(rowBase + r0 + half * 8) * DDD + j0]);
        float bz[2], br[2], bxh[2], brh[2];       // [cc]
#pragma unroll
        for (int cc = 0; cc < 2; cc++) {
            int j = j0 + cc;
            bz[cc]  = __ldg(&g_bias[j]);
            br[cc]  = __ldg(&g_bias[128 + j]);
            bxh[cc] = __ldg(&g_bias[256 + j]);
            brh[cc] = __ldg(&g_bias[384 + j]);
        }

        CP_WAIT0();
        __syncthreads();   // Bs ready

        float acc[6][4];
#pragma unroll
        for (int i = 0; i < 6; i++)
#pragma unroll
            for (int j = 0; j < 4; j++) acc[i][j] = 0.f;

#pragma unroll
        for (int P = 0; P < 8; P++) {
            uint4 A1lo = *reinterpret_cast<const uint4*>(&A1s[r0 * STRIDE_A + P * 16 + 4 * t]);
            uint4 A1hi = *reinterpret_cast<const uint4*>(&A1s[(r0 + 8) * STRIDE_A + P * 16 + 4 * t]);
            uint4 A2lo = *reinterpret_cast<const uint4*>(&A2s[r0 * STRIDE_A + P * 16 + 4 * t]);
            uint4 A2hi = *reinterpret_cast<const uint4*>(&A2s[(r0 + 8) * STRIDE_A + P * 16 + 4 * t]);
#pragma unroll
            for (int oo = 0; oo < 2; oo++) {
                const int o = 2 * P + oo;
                const uint32_t a1_0 = oo ? A1lo.z : A1lo.x;
                const uint32_t a1_1 = oo ? A1hi.z : A1hi.x;
                const uint32_t a1_2 = oo ? A1lo.w : A1lo.y;
                const uint32_t a1_3 = oo ? A1hi.w : A1hi.y;
                const uint32_t a2_0 = oo ? A2lo.z : A2lo.x;
                const uint32_t a2_1 = oo ? A2hi.z : A2hi.x;
                const uint32_t a2_2 = oo ? A2lo.w : A2lo.y;
                const uint32_t a2_3 = oo ? A2hi.w : A2hi.y;
                uint2 bf[6];
#pragma unroll
                for (int mg = 0; mg < 6; mg++)
                    bf[mg] = *reinterpret_cast<const uint2*>(
                        &Bs[((mg * 16 + o) * 16 + n8 * 8 + g) * 8 + 2 * t]);
                MMA8(acc[0], a1_0, a1_1, a1_2, a1_3, bf[0].x, bf[0].y);
                MMA8(acc[1], a1_0, a1_1, a1_2, a1_3, bf[1].x, bf[1].y);
                MMA8(acc[2], a1_0, a1_1, a1_2, a1_3, bf[2].x, bf[2].y);
                MMA8(acc[3], a2_0, a2_1, a2_2, a2_3, bf[3].x, bf[3].y);
                MMA8(acc[4], a2_0, a2_1, a2_2, a2_3, bf[4].x, bf[4].y);
                MMA8(acc[5], a2_0, a2_1, a2_2, a2_3, bf[5].x, bf[5].y);
            }
        }

        // --- GRU epilogue from prefetched operands
#pragma unroll
        for (int half = 0; half < 2; half++) {
            size_t row = rowBase + r0 + half * 8;
            float o2[2];
#pragma unroll
            for (int cc = 0; cc < 2; cc++) {
                int ai = half * 2 + cc;
                float zin = acc[0][ai] + acc[3][ai] + bz[cc];
                float rin = acc[1][ai] + acc[4][ai] + br[cc];
                float xh  = acc[2][ai] + bxh[cc];
                float rh  = acc[5][ai] + brh[cc];
                float z = 1.f / (1.f + __expf(-zin));
                float r = 1.f / (1.f + __expf(-rin));
                float e = __expf(2.f * (xh + r * rh));
                float hh = 1.f - 2.f / (e + 1.f);   // tanh
                float hv = (cc == 0) ? hpre[half].x : hpre[half].y;
                o2[cc] = z * hv + (1.f - z) * hh;
            }
            *reinterpret_cast<float2*>(&out[row * DDD + j0]) =
                make_float2(o2[0], o2[1]);
        }
    }
}

// ---------------------------------------------------------------------------
extern "C" void kernel_launch(void* const* d_in, const int* in_sizes, int n_in,
                              void* d_out, int out_size) {
    const float* atom = (const float*)d_in[0];
    const float* msgs = (const float*)d_in[1];
    const int*   conn = (const int*)d_in[2];
    const float* W1   = (const float*)d_in[3];
    const float* W2   = (const float*)d_in[4];
    const float* bias = (const float*)d_in[5];
    float* out = (float*)d_out;

    zero_kernel<<<16384, 256>>>();
    wprep_kernel<<<384, 256>>>(W1, W2, bias);
    scatter_kernel<<<32768, 256>>>(msgs, conn);

    cudaFuncSetAttribute(fused_gru_kernel,
                         cudaFuncAttributeMaxDynamicSharedMemorySize,
                         SMEM_BYTES);
    fused_gru_kernel<<<MTOT / 128, 512, SMEM_BYTES>>>(atom, out);
}